// round 4
// baseline (speedup 1.0000x reference)
#include <cuda_runtime.h>
#include <math.h>

#define NN 50000
#define NE 400000
#define NG 64
#define DIN 200
#define DH 32
#define NBLK 196   // ceil(NN/256)

// ---------------- scratch (device globals — no allocation allowed) ----------
__device__ __align__(16) float g_tr[NN * DH];      // h @ W_rel (message term)
__device__ __align__(16) float g_agg_a[NN * DH];   // root term + aggregated messages
__device__ __align__(16) float g_agg_b[NN * DH];

// dtype-normalized integer inputs
__device__ int g_srci[NE];
__device__ int g_dsti[NE];
__device__ int g_batchi[NN];
__device__ int g_flag_ei;    // nonzero -> edge_index is int32
__device__ int g_flag_b;     // nonzero -> batch is int32

// CSR-by-dst scratch (built per launch, int-only atomics)
__device__ int g_cnt[NN];
__device__ int g_off[NN + 1];
__device__ int g_cur[NN];
__device__ int g_bsum[256];
__device__ int g_bbase[256];
__device__ int g_esrc[NE];
__device__ int g_gstart[NG + 1];                   // per-graph node ranges (batch sorted)

__device__ __forceinline__ float elu1(float v) { return v > 0.f ? v : expm1f(v); }

// ---------------------------------------------------------------------------
// Integer-input dtype detection + normalization.
// For int64 (values >= 0, < 2^31) the odd 32-bit words are all zero.
// For int32, odd words carry real (mostly nonzero) values. Safe to read only
// `count` words (the int32 interpretation's size).
// ---------------------------------------------------------------------------
__global__ void k_flagzero()
{
    if (threadIdx.x == 0 && blockIdx.x == 0) { g_flag_ei = 0; g_flag_b = 0; }
}

__global__ void k_detect(const unsigned* __restrict__ ei_w,
                         const unsigned* __restrict__ b_w)
{
    const int i = blockIdx.x * blockDim.x + threadIdx.x;
    const int idx = 2 * i + 1;
    unsigned v = 0, u = 0;
    if (idx < 2 * NE) v = ei_w[idx];     // first 800000 words of edge_index
    if (idx < NN)     u = b_w[idx];      // first 50000 words of batch
    const unsigned bv = __ballot_sync(0xffffffffu, v != 0);
    const unsigned bu = __ballot_sync(0xffffffffu, u != 0);
    if ((threadIdx.x & 31) == 0) {
        if (bv) atomicOr(&g_flag_ei, 1);
        if (bu) atomicOr(&g_flag_b, 1);
    }
}

__global__ void k_conv_edges(const void* __restrict__ ei_raw)
{
    const int e = blockIdx.x * blockDim.x + threadIdx.x;
    if (e >= NE) return;
    int s, d;
    if (g_flag_ei) {
        const int* p = (const int*)ei_raw;
        s = p[e]; d = p[NE + e];
    } else {
        const long long* p = (const long long*)ei_raw;
        s = (int)p[e]; d = (int)p[NE + e];
    }
    // clamp defensively so a surprise never wilds an address again
    s &= 0x7fffffff; d &= 0x7fffffff;
    g_srci[e] = (s < NN) ? s : 0;
    g_dsti[e] = (d < NN) ? d : 0;
}

__global__ void k_conv_batch(const void* __restrict__ b_raw)
{
    const int i = blockIdx.x * blockDim.x + threadIdx.x;
    if (i >= NN) return;
    int g;
    if (g_flag_b) g = ((const int*)b_raw)[i];
    else          g = (int)((const long long*)b_raw)[i];
    g &= 0x7fffffff;
    g_batchi[i] = (g < NG) ? g : (NG - 1);
}

// ---------------------------------------------------------------------------
// CSR build: histogram -> 2-level exclusive scan -> scatter  (int atomics only)
// ---------------------------------------------------------------------------
__global__ void k_hist_zero()
{
    const int i = blockIdx.x * blockDim.x + threadIdx.x;
    if (i < NN) g_cnt[i] = 0;
}

__global__ void k_hist()
{
    const int e = blockIdx.x * blockDim.x + threadIdx.x;
    if (e >= NE) return;
    atomicAdd(&g_cnt[g_dsti[e]], 1);
}

__global__ void k_scan_block()
{
    __shared__ int s[256];
    const int tid = threadIdx.x;
    const int i = blockIdx.x * 256 + tid;
    const int v = (i < NN) ? g_cnt[i] : 0;
    s[tid] = v;
    __syncthreads();
#pragma unroll
    for (int d = 1; d < 256; d <<= 1) {
        const int t = (tid >= d) ? s[tid - d] : 0;
        __syncthreads();
        s[tid] += t;
        __syncthreads();
    }
    if (i < NN) g_off[i] = s[tid] - v;           // exclusive within block
    if (tid == 255) g_bsum[blockIdx.x] = s[255]; // block total
}

__global__ void k_scan_top()
{
    __shared__ int s[256];
    const int tid = threadIdx.x;
    const int v = (tid < NBLK) ? g_bsum[tid] : 0;
    s[tid] = v;
    __syncthreads();
#pragma unroll
    for (int d = 1; d < 256; d <<= 1) {
        const int t = (tid >= d) ? s[tid - d] : 0;
        __syncthreads();
        s[tid] += t;
        __syncthreads();
    }
    g_bbase[tid] = s[tid] - v;                   // exclusive block bases
}

__global__ void k_scan_add()
{
    const int i = blockIdx.x * blockDim.x + threadIdx.x;
    if (i < NN) {
        const int o = g_off[i] + g_bbase[i >> 8];
        g_off[i] = o;
        g_cur[i] = o;
    }
    if (i == 0) g_off[NN] = NE;
}

__global__ void k_scatter()
{
    const int e = blockIdx.x * blockDim.x + threadIdx.x;
    if (e >= NE) return;
    const int pos = atomicAdd(&g_cur[g_dsti[e]], 1);
    g_esrc[pos] = g_srci[e];
}

// ---------------------------------------------------------------------------
// Graph boundaries from sorted batch (plain stores, no atomics)
// ---------------------------------------------------------------------------
__global__ void k_bounds()
{
    const int i = blockIdx.x * blockDim.x + threadIdx.x;
    if (i >= NN) return;
    const int g  = g_batchi[i];
    const int gp = (i == 0) ? -1 : g_batchi[i - 1];
    for (int q = gp + 1; q <= g; q++) g_gstart[q] = i;      // covers empty graphs
    if (i == NN - 1)
        for (int q = g + 1; q <= NG; q++) g_gstart[q] = NN;
}

// ---------------------------------------------------------------------------
// GEMM1: t = x[50000,200] @ [Wr | Wl][200,64]
//   cols 0..31  -> g_tr       (x @ W1r)
//   cols 32..63 -> g_agg_a    (x @ W1l + b1)   [root term pre-seeded]
// ---------------------------------------------------------------------------
__global__ __launch_bounds__(256) void k_gemm1(const float* __restrict__ x,
                                               const float* __restrict__ Wr,
                                               const float* __restrict__ Wl,
                                               const float* __restrict__ b)
{
    __shared__ __align__(16) float Xs[8 * 256];   // [k][node], transposed
    __shared__ __align__(16) float Wsc[8 * 64];   // [k][col]
    __shared__ float bs[32];

    const int tid = threadIdx.x;
    const int n0  = blockIdx.x * 256;
    if (tid < 32) bs[tid] = b[tid];

    const int cg = tid & 7;        // col group (8 cols) — fastest for broadcast
    const int ng = tid >> 3;       // node group (8 nodes)

    float acc[8][8];
#pragma unroll
    for (int i = 0; i < 8; i++)
#pragma unroll
        for (int j = 0; j < 8; j++) acc[i][j] = 0.f;

    const int  nld = n0 + tid;
    const bool vld = nld < NN;
    const float4* xrow = reinterpret_cast<const float4*>(x + (long)nld * DIN);
    const int kidx = tid >> 6, cidx = tid & 63;

    for (int k0 = 0; k0 < DIN; k0 += 8) {
        float4 xa = make_float4(0.f, 0.f, 0.f, 0.f), xb = xa;
        if (vld) { xa = xrow[k0 >> 2]; xb = xrow[(k0 >> 2) + 1]; }
        const int k1 = k0 + kidx, k2 = k1 + 4;
        const float w1 = (cidx < 32) ? Wr[k1 * 32 + cidx] : Wl[k1 * 32 + cidx - 32];
        const float w2 = (cidx < 32) ? Wr[k2 * 32 + cidx] : Wl[k2 * 32 + cidx - 32];

        __syncthreads();
        Xs[0 * 256 + tid] = xa.x; Xs[1 * 256 + tid] = xa.y;
        Xs[2 * 256 + tid] = xa.z; Xs[3 * 256 + tid] = xa.w;
        Xs[4 * 256 + tid] = xb.x; Xs[5 * 256 + tid] = xb.y;
        Xs[6 * 256 + tid] = xb.z; Xs[7 * 256 + tid] = xb.w;
        Wsc[kidx * 64 + cidx]       = w1;
        Wsc[(kidx + 4) * 64 + cidx] = w2;
        __syncthreads();

#pragma unroll
        for (int kk = 0; kk < 8; kk++) {
            const float4* xp = reinterpret_cast<const float4*>(Xs + kk * 256 + ng * 8);
            const float4 a0 = xp[0], a1 = xp[1];
            const float4* wp = reinterpret_cast<const float4*>(Wsc + kk * 64 + cg * 8);
            const float4 b0 = wp[0], b1 = wp[1];
            const float xv[8] = {a0.x, a0.y, a0.z, a0.w, a1.x, a1.y, a1.z, a1.w};
            const float wv[8] = {b0.x, b0.y, b0.z, b0.w, b1.x, b1.y, b1.z, b1.w};
#pragma unroll
            for (int i = 0; i < 8; i++)
#pragma unroll
                for (int j = 0; j < 8; j++) acc[i][j] += xv[i] * wv[j];
        }
    }

    const int c0 = cg * 8;
#pragma unroll
    for (int i = 0; i < 8; i++) {
        const int node = n0 + ng * 8 + i;
        if (node >= NN) continue;
        float4 lo = make_float4(acc[i][0], acc[i][1], acc[i][2], acc[i][3]);
        float4 hi = make_float4(acc[i][4], acc[i][5], acc[i][6], acc[i][7]);
        if (cg < 4) {
            *reinterpret_cast<float4*>(g_tr + node * DH + c0)     = lo;
            *reinterpret_cast<float4*>(g_tr + node * DH + c0 + 4) = hi;
        } else {
            const int cc = c0 - 32;
            lo.x += bs[cc + 0]; lo.y += bs[cc + 1]; lo.z += bs[cc + 2]; lo.w += bs[cc + 3];
            hi.x += bs[cc + 4]; hi.y += bs[cc + 5]; hi.z += bs[cc + 6]; hi.w += bs[cc + 7];
            *reinterpret_cast<float4*>(g_agg_a + node * DH + cc)     = lo;
            *reinterpret_cast<float4*>(g_agg_a + node * DH + cc + 4) = hi;
        }
    }
}

// ---------------------------------------------------------------------------
// Small GEMM (layers 2,3): h = elu(agg_in); g_tr = h@Wr; agg_out = h@Wl + b
// ---------------------------------------------------------------------------
__global__ __launch_bounds__(256) void k_gemm_small(int insel,
                                                    const float* __restrict__ Wr,
                                                    const float* __restrict__ Wl,
                                                    const float* __restrict__ b)
{
    __shared__ __align__(16) float Ws[32 * 64];
    __shared__ float bs[32];
    const int tid = threadIdx.x;
    for (int i = tid; i < 2048; i += 256) {
        const int k = i >> 6, c = i & 63;
        Ws[i] = (c < 32) ? Wr[k * 32 + c] : Wl[k * 32 + c - 32];
    }
    if (tid < 32) bs[tid] = b[tid];
    __syncthreads();

    const int node = blockIdx.x * 256 + tid;
    if (node >= NN) return;

    const float* hin  = insel ? g_agg_b : g_agg_a;
    float*       aout = insel ? g_agg_a : g_agg_b;

    float xr[32];
    const float4* hp = reinterpret_cast<const float4*>(hin + node * DH);
#pragma unroll
    for (int q = 0; q < 8; q++) {
        const float4 v = hp[q];
        xr[q * 4 + 0] = elu1(v.x); xr[q * 4 + 1] = elu1(v.y);
        xr[q * 4 + 2] = elu1(v.z); xr[q * 4 + 3] = elu1(v.w);
    }

    float4 acc[16];
#pragma unroll
    for (int i = 0; i < 16; i++) acc[i] = make_float4(0.f, 0.f, 0.f, 0.f);
#pragma unroll
    for (int k = 0; k < 32; k++) {
        const float xk = xr[k];
        const float4* wp = reinterpret_cast<const float4*>(Ws + k * 64);
#pragma unroll
        for (int cq = 0; cq < 16; cq++) {
            const float4 w = wp[cq];
            acc[cq].x += xk * w.x; acc[cq].y += xk * w.y;
            acc[cq].z += xk * w.z; acc[cq].w += xk * w.w;
        }
    }

    float4* trp = reinterpret_cast<float4*>(g_tr + node * DH);
#pragma unroll
    for (int cq = 0; cq < 8; cq++) trp[cq] = acc[cq];
    float4* ap = reinterpret_cast<float4*>(aout + node * DH);
#pragma unroll
    for (int cq = 0; cq < 8; cq++) {
        float4 v = acc[8 + cq];
        v.x += bs[cq * 4 + 0]; v.y += bs[cq * 4 + 1];
        v.z += bs[cq * 4 + 2]; v.w += bs[cq * 4 + 3];
        ap[cq] = v;
    }
}

// ---------------------------------------------------------------------------
// Edge aggregation (gather, no atomics): warp per dst node, lane = col.
// agg[node] += sum over in-edges of g_tr[src]
// ---------------------------------------------------------------------------
__global__ __launch_bounds__(256) void k_aggr(int sel)
{
    const int gw   = (blockIdx.x * 256 + threadIdx.x) >> 5;
    const int lane = threadIdx.x & 31;
    if (gw >= NN) return;

    const int beg = g_off[gw];
    const int end = g_off[gw + 1];
    float acc = 0.f;

    int k = beg;
    for (; k + 3 < end; k += 4) {               // MLP=4 over L2-latency gathers
        const int s0 = g_esrc[k + 0];
        const int s1 = g_esrc[k + 1];
        const int s2 = g_esrc[k + 2];
        const int s3 = g_esrc[k + 3];
        const float v0 = g_tr[s0 * DH + lane];
        const float v1 = g_tr[s1 * DH + lane];
        const float v2 = g_tr[s2 * DH + lane];
        const float v3 = g_tr[s3 * DH + lane];
        acc += v0 + v1 + v2 + v3;
    }
    for (; k < end; k++)
        acc += g_tr[g_esrc[k] * DH + lane];

    float* agg = sel ? g_agg_b : g_agg_a;
    agg[gw * DH + lane] += acc;                 // owner RMW — no atomics
}

// ---------------------------------------------------------------------------
// Fused pool + head: block per graph, deterministic reduction (no atomics).
// ---------------------------------------------------------------------------
__global__ __launch_bounds__(256) void k_poolhead(const float* __restrict__ Wlin,
                                                  const float* __restrict__ blin,
                                                  float* __restrict__ out)
{
    __shared__ float sp[8][32];
    __shared__ float pooled[32];

    const int gph  = blockIdx.x;
    const int tid  = threadIdx.x;
    const int w    = tid >> 5;
    const int lane = tid & 31;

    const int beg = g_gstart[gph];
    const int end = g_gstart[gph + 1];

    float acc = 0.f;
    for (int row = beg + w; row < end; row += 8)
        acc += elu1(g_agg_a[row * DH + lane]);   // coalesced 128B rows
    sp[w][lane] = acc;
    __syncthreads();

    if (tid < 32) {
        float s = 0.f;
#pragma unroll
        for (int i = 0; i < 8; i++) s += sp[i][tid];
        const int cnt = end - beg;
        const float inv = 1.f / fmaxf((float)cnt, 1.f);
        pooled[tid] = s * inv;
    }
    __syncthreads();

    if (tid == 0) {
        float l0 = blin[0], l1 = blin[1];
#pragma unroll
        for (int c = 0; c < DH; c++) {
            const float p = pooled[c];
            l0 += p * Wlin[c * 2 + 0];
            l1 += p * Wlin[c * 2 + 1];
        }
        const float m   = fmaxf(l0, l1);
        const float lse = m + logf(expf(l0 - m) + expf(l1 - m));
        out[gph * 2 + 0] = l0 - lse;
        out[gph * 2 + 1] = l1 - lse;
    }
}

// ---------------------------------------------------------------------------
extern "C" void kernel_launch(void* const* d_in, const int* in_sizes, int n_in,
                              void* d_out, int out_size)
{
    // ---- locate inputs by element count (robust to slot permutation) ----
    const void *p_x = 0, *p_ei = 0, *p_batch = 0;
    const void *p_W1[2] = {0, 0};         // W1r, W1l (order of appearance)
    const void *p_W23[4] = {0, 0, 0, 0};  // W2r, W2l, W3r, W3l
    const void *p_b[3] = {0, 0, 0};       // b1, b2, b3
    const void *p_Wlin = 0, *p_blin = 0;
    int n64 = 0, n1024 = 0, n32 = 0;
    for (int i = 0; i < n_in; i++) {
        const int s = in_sizes[i];
        if      (s == NN * DIN) p_x = d_in[i];
        else if (s == 2 * NE)   p_ei = d_in[i];
        else if (s == NN)       p_batch = d_in[i];
        else if (s == DIN * DH) { if (n64 < 2) p_W1[n64++] = d_in[i]; }
        else if (s == DH * DH)  { if (n1024 < 4) p_W23[n1024++] = d_in[i]; }
        else if (s == DH)       { if (n32 < 3) p_b[n32++] = d_in[i]; }
        else if (s == DH * 2)   p_Wlin = d_in[i];
        else if (s == 2)        p_blin = d_in[i];
        // s == NE (edge_attr) intentionally ignored
    }
    const float* x    = (const float*)p_x;
    const float* W1r  = (const float*)p_W1[0];
    const float* W1l  = (const float*)p_W1[1];
    const float* b1   = (const float*)p_b[0];
    const float* W2r  = (const float*)p_W23[0];
    const float* W2l  = (const float*)p_W23[1];
    const float* b2   = (const float*)p_b[1];
    const float* W3r  = (const float*)p_W23[2];
    const float* W3l  = (const float*)p_W23[3];
    const float* b3   = (const float*)p_b[2];
    const float* Wlin = (const float*)p_Wlin;
    const float* blin = (const float*)p_blin;
    float* out = (float*)d_out;

    const int NODE_BLKS = NBLK;                   // 196
    const int EDGE_BLKS = (NE + 255) / 256;       // 1563
    const int AGGR_BLKS = (NN * 32 + 255) / 256;  // 6250

    // ---- dtype detect + normalize integer inputs ----
    k_flagzero<<<1, 32>>>();
    k_detect<<<EDGE_BLKS, 256>>>((const unsigned*)p_ei, (const unsigned*)p_batch);
    k_conv_edges<<<EDGE_BLKS, 256>>>(p_ei);
    k_conv_batch<<<NODE_BLKS, 256>>>(p_batch);

    // ---- CSR build (int atomics only) + graph boundaries ----
    k_hist_zero<<<NODE_BLKS, 256>>>();
    k_hist<<<EDGE_BLKS, 256>>>();
    k_scan_block<<<NODE_BLKS, 256>>>();
    k_scan_top<<<1, 256>>>();
    k_scan_add<<<NODE_BLKS, 256>>>();
    k_scatter<<<EDGE_BLKS, 256>>>();
    k_bounds<<<NODE_BLKS, 256>>>();

    // ---- Layer 1 ----
    k_gemm1<<<NODE_BLKS, 256>>>(x, W1r, W1l, b1);
    k_aggr<<<AGGR_BLKS, 256>>>(0);
    // ---- Layer 2 (reads agg_a, writes agg_b) ----
    k_gemm_small<<<NODE_BLKS, 256>>>(0, W2r, W2l, b2);
    k_aggr<<<AGGR_BLKS, 256>>>(1);
    // ---- Layer 3 (reads agg_b, writes agg_a) ----
    k_gemm_small<<<NODE_BLKS, 256>>>(1, W3r, W3l, b3);
    k_aggr<<<AGGR_BLKS, 256>>>(0);
    // ---- Fused pool + head (deterministic, atomic-free) ----
    k_poolhead<<<NG, 256>>>(Wlin, blin, out);
}

// round 5
// speedup vs baseline: 1.0438x; 1.0438x over previous
#include <cuda_runtime.h>
#include <math.h>

#define NN 50000
#define NE 400000
#define NG 64
#define DIN 200
#define DH 32
#define NBLK 196   // ceil(NN/256)

// ---------------- scratch (device globals — no allocation allowed) ----------
__device__ __align__(16) float g_tr[NN * DH];      // h @ W_rel (message term)
__device__ __align__(16) float g_agg_a[NN * DH];   // root term + aggregated messages
__device__ __align__(16) float g_agg_b[NN * DH];

__device__ int g_srci[NE];
__device__ int g_dsti[NE];
__device__ int g_flag_ei;    // nonzero -> edge_index is int32
__device__ int g_flag_b;     // nonzero -> batch is int32

__device__ int g_cnt[NN];
__device__ int g_off[NN + 1];
__device__ int g_cur[NN];
__device__ int g_bsum[256];
__device__ int g_bbase[256];
__device__ int g_esrc[NE];
__device__ int g_gstart[NG + 1];

__device__ __forceinline__ float elu1(float v) { return v > 0.f ? v : expm1f(v); }

#define FMA_X2(acc, a, b) \
    asm("fma.rn.f32x2 %0, %1, %2, %0;" : "+l"(acc) : "l"(a), "l"(b))
#define DUP_X2(out, x) \
    asm("mov.b64 %0, {%1, %1};" : "=l"(out) : "r"(__float_as_uint(x)))
#define UNPK_X2(lo, hi, in) \
    asm("mov.b64 {%0, %1}, %2;" : "=f"(lo), "=f"(hi) : "l"(in))

// ---------------------------------------------------------------------------
// Fused: dtype detection (block 0, sampling) + g_cnt zeroing (all blocks).
// int64 non-negative values < 2^31 have zero odd 32-bit words; int32 values
// (random src ids / tail batch ids ~63) are essentially never all zero.
// ---------------------------------------------------------------------------
__global__ void k_detect_zero(const unsigned* __restrict__ ei_w,
                              const unsigned* __restrict__ b_w)
{
    const int i = blockIdx.x * blockDim.x + threadIdx.x;
    if (i < NN) g_cnt[i] = 0;

    if (blockIdx.x == 0) {
        __shared__ int s_ei, s_b;
        const int tid = threadIdx.x;
        if (tid == 0) { s_ei = 0; s_b = 0; }
        __syncthreads();
        // edge_index: 256 samples spread over the first 800000 words
        {
            const int k = tid * 1562;              // 2k+1 <= 799945 < 800000
            if (ei_w[2 * k + 1] != 0) atomicOr(&s_ei, 1);
        }
        // batch: 256 samples in the sorted tail (values ~ NG-1)
        {
            const int k = 24744 + tid;             // 2k+1 in [49489, 49999]
            if (b_w[2 * k + 1] != 0) atomicOr(&s_b, 1);
        }
        __syncthreads();
        if (tid == 0) { g_flag_ei = s_ei; g_flag_b = s_b; }
    }
}

// ---------------------------------------------------------------------------
// Fused: decode edges (either dtype) + clamp + dst histogram
// ---------------------------------------------------------------------------
__global__ void k_conv_hist(const void* __restrict__ ei_raw)
{
    const int e = blockIdx.x * blockDim.x + threadIdx.x;
    if (e >= NE) return;
    int s, d;
    if (g_flag_ei) {
        const int* p = (const int*)ei_raw;
        s = p[e]; d = p[NE + e];
    } else {
        const long long* p = (const long long*)ei_raw;
        s = (int)p[e]; d = (int)p[NE + e];
    }
    s &= 0x7fffffff; d &= 0x7fffffff;
    s = (s < NN) ? s : 0;
    d = (d < NN) ? d : 0;
    g_srci[e] = s;
    g_dsti[e] = d;
    atomicAdd(&g_cnt[d], 1);
}

// ---------------------------------------------------------------------------
// Exclusive scan (2-level) + scatter
// ---------------------------------------------------------------------------
__global__ void k_scan_block()
{
    __shared__ int s[256];
    const int tid = threadIdx.x;
    const int i = blockIdx.x * 256 + tid;
    const int v = (i < NN) ? g_cnt[i] : 0;
    s[tid] = v;
    __syncthreads();
#pragma unroll
    for (int d = 1; d < 256; d <<= 1) {
        const int t = (tid >= d) ? s[tid - d] : 0;
        __syncthreads();
        s[tid] += t;
        __syncthreads();
    }
    if (i < NN) g_off[i] = s[tid] - v;
    if (tid == 255) g_bsum[blockIdx.x] = s[255];
}

__global__ void k_scan_top()
{
    __shared__ int s[256];
    const int tid = threadIdx.x;
    const int v = (tid < NBLK) ? g_bsum[tid] : 0;
    s[tid] = v;
    __syncthreads();
#pragma unroll
    for (int d = 1; d < 256; d <<= 1) {
        const int t = (tid >= d) ? s[tid - d] : 0;
        __syncthreads();
        s[tid] += t;
        __syncthreads();
    }
    g_bbase[tid] = s[tid] - v;
}

__global__ void k_scan_add()
{
    const int i = blockIdx.x * blockDim.x + threadIdx.x;
    if (i < NN) {
        const int o = g_off[i] + g_bbase[i >> 8];
        g_off[i] = o;
        g_cur[i] = o;
    }
    if (i == 0) g_off[NN] = NE;
}

__global__ void k_scatter()
{
    const int e = blockIdx.x * blockDim.x + threadIdx.x;
    if (e >= NE) return;
    const int pos = atomicAdd(&g_cur[g_dsti[e]], 1);
    g_esrc[pos] = g_srci[e];
}

// ---------------------------------------------------------------------------
// Graph boundaries directly from raw sorted batch (dtype-aware, no atomics)
// ---------------------------------------------------------------------------
__device__ __forceinline__ int batch_at(const void* b_raw, int i, int is32)
{
    int g = is32 ? ((const int*)b_raw)[i] : (int)((const long long*)b_raw)[i];
    g &= 0x7fffffff;
    return (g < NG) ? g : (NG - 1);
}

__global__ void k_bounds(const void* __restrict__ b_raw)
{
    const int i = blockIdx.x * blockDim.x + threadIdx.x;
    if (i >= NN) return;
    const int is32 = g_flag_b;
    const int g  = batch_at(b_raw, i, is32);
    const int gp = (i == 0) ? -1 : batch_at(b_raw, i - 1, is32);
    for (int q = gp + 1; q <= g; q++) g_gstart[q] = i;
    if (i == NN - 1)
        for (int q = g + 1; q <= NG; q++) g_gstart[q] = NN;
}

// ---------------------------------------------------------------------------
// GEMM1: [50000,200] @ [Wr|Wl][200,64] with packed fma.rn.f32x2
//   cols 0..31  -> g_tr ;  cols 32..63 -> g_agg_a (+bias, root term)
// ---------------------------------------------------------------------------
__global__ __launch_bounds__(256) void k_gemm1(const float* __restrict__ x,
                                               const float* __restrict__ Wr,
                                               const float* __restrict__ Wl,
                                               const float* __restrict__ b)
{
    __shared__ __align__(16) float Xs[8 * 256];   // [k][node]
    __shared__ __align__(16) float Wsc[8 * 64];   // [k][col]
    __shared__ float bs[32];

    const int tid = threadIdx.x;
    const int n0  = blockIdx.x * 256;
    if (tid < 32) bs[tid] = b[tid];

    const int cg = tid & 7;        // col group (8 cols = 4 packed pairs)
    const int ng = tid >> 3;       // node group (8 nodes)

    unsigned long long acc2[8][4];
#pragma unroll
    for (int i = 0; i < 8; i++)
#pragma unroll
        for (int j = 0; j < 4; j++) acc2[i][j] = 0ULL;

    const int  nld = n0 + tid;
    const bool vld = nld < NN;
    const float4* xrow = reinterpret_cast<const float4*>(x + (long)nld * DIN);
    const int kidx = tid >> 6, cidx = tid & 63;

    for (int k0 = 0; k0 < DIN; k0 += 8) {
        float4 xa = make_float4(0.f, 0.f, 0.f, 0.f), xb = xa;
        if (vld) { xa = xrow[k0 >> 2]; xb = xrow[(k0 >> 2) + 1]; }
        const int k1 = k0 + kidx, k2 = k1 + 4;
        const float w1 = (cidx < 32) ? Wr[k1 * 32 + cidx] : Wl[k1 * 32 + cidx - 32];
        const float w2 = (cidx < 32) ? Wr[k2 * 32 + cidx] : Wl[k2 * 32 + cidx - 32];

        __syncthreads();
        Xs[0 * 256 + tid] = xa.x; Xs[1 * 256 + tid] = xa.y;
        Xs[2 * 256 + tid] = xa.z; Xs[3 * 256 + tid] = xa.w;
        Xs[4 * 256 + tid] = xb.x; Xs[5 * 256 + tid] = xb.y;
        Xs[6 * 256 + tid] = xb.z; Xs[7 * 256 + tid] = xb.w;
        Wsc[kidx * 64 + cidx]       = w1;
        Wsc[(kidx + 4) * 64 + cidx] = w2;
        __syncthreads();

#pragma unroll
        for (int kk = 0; kk < 8; kk++) {
            const float4* xp = reinterpret_cast<const float4*>(Xs + kk * 256 + ng * 8);
            const float4 a0 = xp[0], a1 = xp[1];
            const unsigned long long* wp =
                reinterpret_cast<const unsigned long long*>(Wsc + kk * 64 + cg * 8);
            const unsigned long long w0 = wp[0], w1p = wp[1], w2p = wp[2], w3p = wp[3];
            const float xv[8] = {a0.x, a0.y, a0.z, a0.w, a1.x, a1.y, a1.z, a1.w};
#pragma unroll
            for (int i = 0; i < 8; i++) {
                unsigned long long xd;
                DUP_X2(xd, xv[i]);                 // alu pipe, overlaps fma pipe
                FMA_X2(acc2[i][0], xd, w0);
                FMA_X2(acc2[i][1], xd, w1p);
                FMA_X2(acc2[i][2], xd, w2p);
                FMA_X2(acc2[i][3], xd, w3p);
            }
        }
    }

    const int c0 = cg * 8;
#pragma unroll
    for (int i = 0; i < 8; i++) {
        const int node = n0 + ng * 8 + i;
        if (node >= NN) continue;
        float c[8];
#pragma unroll
        for (int j = 0; j < 4; j++) UNPK_X2(c[2 * j], c[2 * j + 1], acc2[i][j]);
        float4 lo = make_float4(c[0], c[1], c[2], c[3]);
        float4 hi = make_float4(c[4], c[5], c[6], c[7]);
        if (cg < 4) {
            *reinterpret_cast<float4*>(g_tr + node * DH + c0)     = lo;
            *reinterpret_cast<float4*>(g_tr + node * DH + c0 + 4) = hi;
        } else {
            const int cc = c0 - 32;
            lo.x += bs[cc + 0]; lo.y += bs[cc + 1]; lo.z += bs[cc + 2]; lo.w += bs[cc + 3];
            hi.x += bs[cc + 4]; hi.y += bs[cc + 5]; hi.z += bs[cc + 6]; hi.w += bs[cc + 7];
            *reinterpret_cast<float4*>(g_agg_a + node * DH + cc)     = lo;
            *reinterpret_cast<float4*>(g_agg_a + node * DH + cc + 4) = hi;
        }
    }
}

// ---------------------------------------------------------------------------
// Small GEMM (layers 2,3), f32x2 packed: h = elu(in); tr = h@Wr; out = h@Wl + b
// ---------------------------------------------------------------------------
__global__ __launch_bounds__(256) void k_gemm_small(int insel,
                                                    const float* __restrict__ Wr,
                                                    const float* __restrict__ Wl,
                                                    const float* __restrict__ b)
{
    __shared__ __align__(16) float Ws[32 * 64];
    __shared__ float bs[32];
    const int tid = threadIdx.x;
    for (int i = tid; i < 2048; i += 256) {
        const int k = i >> 6, c = i & 63;
        Ws[i] = (c < 32) ? Wr[k * 32 + c] : Wl[k * 32 + c - 32];
    }
    if (tid < 32) bs[tid] = b[tid];
    __syncthreads();

    const int node = blockIdx.x * 256 + tid;
    if (node >= NN) return;

    const float* hin  = insel ? g_agg_b : g_agg_a;
    float*       aout = insel ? g_agg_a : g_agg_b;

    float xr[32];
    const float4* hp = reinterpret_cast<const float4*>(hin + node * DH);
#pragma unroll
    for (int q = 0; q < 8; q++) {
        const float4 v = hp[q];
        xr[q * 4 + 0] = elu1(v.x); xr[q * 4 + 1] = elu1(v.y);
        xr[q * 4 + 2] = elu1(v.z); xr[q * 4 + 3] = elu1(v.w);
    }

    unsigned long long acc2[32];
#pragma unroll
    for (int i = 0; i < 32; i++) acc2[i] = 0ULL;

#pragma unroll
    for (int k = 0; k < 32; k++) {
        unsigned long long xd;
        DUP_X2(xd, xr[k]);
        const unsigned long long* wp =
            reinterpret_cast<const unsigned long long*>(Ws + k * 64);  // broadcast
#pragma unroll
        for (int p = 0; p < 32; p++) FMA_X2(acc2[p], xd, wp[p]);
    }

    float c[64];
#pragma unroll
    for (int p = 0; p < 32; p++) UNPK_X2(c[2 * p], c[2 * p + 1], acc2[p]);

    float4* trp = reinterpret_cast<float4*>(g_tr + node * DH);
#pragma unroll
    for (int q = 0; q < 8; q++)
        trp[q] = make_float4(c[q * 4 + 0], c[q * 4 + 1], c[q * 4 + 2], c[q * 4 + 3]);
    float4* ap = reinterpret_cast<float4*>(aout + node * DH);
#pragma unroll
    for (int q = 0; q < 8; q++)
        ap[q] = make_float4(c[32 + q * 4 + 0] + bs[q * 4 + 0],
                            c[32 + q * 4 + 1] + bs[q * 4 + 1],
                            c[32 + q * 4 + 2] + bs[q * 4 + 2],
                            c[32 + q * 4 + 3] + bs[q * 4 + 3]);
}

// ---------------------------------------------------------------------------
// Edge aggregation (gather, no atomics): warp per dst node, lane = col.
// ---------------------------------------------------------------------------
__global__ __launch_bounds__(256) void k_aggr(int sel)
{
    const int gw   = (blockIdx.x * 256 + threadIdx.x) >> 5;
    const int lane = threadIdx.x & 31;
    if (gw >= NN) return;

    const int beg = g_off[gw];
    const int end = g_off[gw + 1];
    float acc = 0.f;

    int k = beg;
    for (; k + 3 < end; k += 4) {
        const int s0 = g_esrc[k + 0];
        const int s1 = g_esrc[k + 1];
        const int s2 = g_esrc[k + 2];
        const int s3 = g_esrc[k + 3];
        const float v0 = g_tr[s0 * DH + lane];
        const float v1 = g_tr[s1 * DH + lane];
        const float v2 = g_tr[s2 * DH + lane];
        const float v3 = g_tr[s3 * DH + lane];
        acc += v0 + v1 + v2 + v3;
    }
    for (; k < end; k++)
        acc += g_tr[g_esrc[k] * DH + lane];

    float* agg = sel ? g_agg_b : g_agg_a;
    agg[gw * DH + lane] += acc;
}

// ---------------------------------------------------------------------------
// Fused pool + head (deterministic, atomic-free)
// ---------------------------------------------------------------------------
__global__ __launch_bounds__(256) void k_poolhead(const float* __restrict__ Wlin,
                                                  const float* __restrict__ blin,
                                                  float* __restrict__ out)
{
    __shared__ float sp[8][32];
    __shared__ float pooled[32];

    const int gph  = blockIdx.x;
    const int tid  = threadIdx.x;
    const int w    = tid >> 5;
    const int lane = tid & 31;

    const int beg = g_gstart[gph];
    const int end = g_gstart[gph + 1];

    float acc = 0.f;
    for (int row = beg + w; row < end; row += 8)
        acc += elu1(g_agg_a[row * DH + lane]);
    sp[w][lane] = acc;
    __syncthreads();

    if (tid < 32) {
        float s = 0.f;
#pragma unroll
        for (int i = 0; i < 8; i++) s += sp[i][tid];
        const int cnt = end - beg;
        pooled[tid] = s / fmaxf((float)cnt, 1.f);
    }
    __syncthreads();

    if (tid == 0) {
        float l0 = blin[0], l1 = blin[1];
#pragma unroll
        for (int c = 0; c < DH; c++) {
            const float p = pooled[c];
            l0 += p * Wlin[c * 2 + 0];
            l1 += p * Wlin[c * 2 + 1];
        }
        const float m   = fmaxf(l0, l1);
        const float lse = m + logf(expf(l0 - m) + expf(l1 - m));
        out[gph * 2 + 0] = l0 - lse;
        out[gph * 2 + 1] = l1 - lse;
    }
}

// ---------------------------------------------------------------------------
extern "C" void kernel_launch(void* const* d_in, const int* in_sizes, int n_in,
                              void* d_out, int out_size)
{
    const void *p_x = 0, *p_ei = 0, *p_batch = 0;
    const void *p_W1[2] = {0, 0};
    const void *p_W23[4] = {0, 0, 0, 0};
    const void *p_b[3] = {0, 0, 0};
    const void *p_Wlin = 0, *p_blin = 0;
    int n64 = 0, n1024 = 0, n32 = 0;
    for (int i = 0; i < n_in; i++) {
        const int s = in_sizes[i];
        if      (s == NN * DIN) p_x = d_in[i];
        else if (s == 2 * NE)   p_ei = d_in[i];
        else if (s == NN)       p_batch = d_in[i];
        else if (s == DIN * DH) { if (n64 < 2) p_W1[n64++] = d_in[i]; }
        else if (s == DH * DH)  { if (n1024 < 4) p_W23[n1024++] = d_in[i]; }
        else if (s == DH)       { if (n32 < 3) p_b[n32++] = d_in[i]; }
        else if (s == DH * 2)   p_Wlin = d_in[i];
        else if (s == 2)        p_blin = d_in[i];
    }
    const float* x    = (const float*)p_x;
    const float* W1r  = (const float*)p_W1[0];
    const float* W1l  = (const float*)p_W1[1];
    const float* b1   = (const float*)p_b[0];
    const float* W2r  = (const float*)p_W23[0];
    const float* W2l  = (const float*)p_W23[1];
    const float* b2   = (const float*)p_b[1];
    const float* W3r  = (const float*)p_W23[2];
    const float* W3l  = (const float*)p_W23[3];
    const float* b3   = (const float*)p_b[2];
    const float* Wlin = (const float*)p_Wlin;
    const float* blin = (const float*)p_blin;
    float* out = (float*)d_out;

    const int NODE_BLKS = NBLK;                   // 196
    const int EDGE_BLKS = (NE + 255) / 256;       // 1563
    const int AGGR_BLKS = (NN * 32 + 255) / 256;  // 6250

    // Preprocess: detect dtypes + zero hist, decode+hist, scan, scatter, bounds
    k_detect_zero<<<NODE_BLKS, 256>>>((const unsigned*)p_ei, (const unsigned*)p_batch);
    k_conv_hist<<<EDGE_BLKS, 256>>>(p_ei);
    k_scan_block<<<NODE_BLKS, 256>>>();
    k_scan_top<<<1, 256>>>();
    k_scan_add<<<NODE_BLKS, 256>>>();
    k_scatter<<<EDGE_BLKS, 256>>>();
    k_bounds<<<NODE_BLKS, 256>>>(p_batch);

    // Layer 1
    k_gemm1<<<NODE_BLKS, 256>>>(x, W1r, W1l, b1);
    k_aggr<<<AGGR_BLKS, 256>>>(0);
    // Layer 2
    k_gemm_small<<<NODE_BLKS, 256>>>(0, W2r, W2l, b2);
    k_aggr<<<AGGR_BLKS, 256>>>(1);
    // Layer 3
    k_gemm_small<<<NODE_BLKS, 256>>>(1, W3r, W3l, b3);
    k_aggr<<<AGGR_BLKS, 256>>>(0);
    // Pool + head
    k_poolhead<<<NG, 256>>>(Wlin, blin, out);
}

// round 7
// speedup vs baseline: 1.1690x; 1.1199x over previous
#include <cuda_runtime.h>
#include <math.h>

#define NN 50000
#define NE 400000
#define NG 64
#define DIN 200
#define DH 32
#define NBLK 196    // ceil(NN/256)
#define SCBLK 1563  // ceil(NE/256)

// ---------------- scratch (device globals — no allocation allowed) ----------
// NOTE: never pass these as kernel arguments from host code — the host-side
// shadow symbol's address gets passed (and ATS makes it "work" reading zeros).
// Device code must reference them directly, selected by an int flag.
__device__ __align__(16) float g_tr_a[NN * DH];
__device__ __align__(16) float g_tr_b[NN * DH];
__device__ __align__(16) float g_root_a[NN * DH];
__device__ __align__(16) float g_root_b[NN * DH];
__device__ float g_sums[NG * DH];

__device__ int g_srci[NE];
__device__ int g_dsti[NE];
__device__ int g_flag_ei;    // nonzero -> edge_index is int32
__device__ int g_flag_b;     // nonzero -> batch is int32

__device__ int g_cnt[NN];
__device__ int g_off[NN];
__device__ int g_cur[NN];
__device__ int g_total;
__device__ int g_esrc[NE];
__device__ int g_gstart[NG + 1];

__device__ __forceinline__ float elu1(float v) { return v > 0.f ? v : expm1f(v); }

#define FMA_X2(acc, a, b) \
    asm("fma.rn.f32x2 %0, %1, %2, %0;" : "+l"(acc) : "l"(a), "l"(b))
#define DUP_X2(out, x) \
    asm("mov.b64 %0, {%1, %1};" : "=l"(out) : "r"(__float_as_uint(x)))
#define UNPK_X2(lo, hi, in) \
    asm("mov.b64 {%0, %1}, %2;" : "=f"(lo), "=f"(hi) : "l"(in))
#define PACK_X2(out, lo, hi) \
    asm("mov.b64 %0, {%1, %2};" : "=l"(out) : "f"(lo), "f"(hi))

// ---------------------------------------------------------------------------
// Kernel 1: zero scratch + dtype detection (block 0 samples odd 32-bit words:
// int64 values < 2^31 have zero high words; int32 payloads essentially never do)
// ---------------------------------------------------------------------------
__global__ void k_detect_zero(const unsigned* __restrict__ ei_w,
                              const unsigned* __restrict__ b_w)
{
    const int i = blockIdx.x * blockDim.x + threadIdx.x;
    if (i < NN) g_cnt[i] = 0;
    if (i < NG * DH) g_sums[i] = 0.f;
    if (i == 0) g_total = 0;

    if (blockIdx.x == 0) {
        __shared__ int s_ei, s_b;
        const int tid = threadIdx.x;
        if (tid == 0) { s_ei = 0; s_b = 0; }
        __syncthreads();
        { const int k = tid * 1562;  if (ei_w[2 * k + 1] != 0) atomicOr(&s_ei, 1); }
        { const int k = 24744 + tid; if (b_w[2 * k + 1] != 0)  atomicOr(&s_b, 1); }
        __syncthreads();
        if (tid == 0) { g_flag_ei = s_ei; g_flag_b = s_b; }
    }
}

// ---------------------------------------------------------------------------
// Kernel 2: decode edges (either dtype) + clamp + dst histogram
// ---------------------------------------------------------------------------
__global__ void k_conv_hist(const void* __restrict__ ei_raw)
{
    const int e = blockIdx.x * blockDim.x + threadIdx.x;
    if (e >= NE) return;
    int s, d;
    if (g_flag_ei) {
        const int* p = (const int*)ei_raw;
        s = p[e]; d = p[NE + e];
    } else {
        const long long* p = (const long long*)ei_raw;
        s = (int)p[e]; d = (int)p[NE + e];
    }
    s &= 0x7fffffff; d &= 0x7fffffff;
    s = (s < NN) ? s : 0;
    d = (d < NN) ? d : 0;
    g_srci[e] = s;
    g_dsti[e] = d;
    atomicAdd(&g_cnt[d], 1);
}

// ---------------------------------------------------------------------------
// Kernel 3: single-pass scan (block scan + atomic base; bases need not be
// monotone since consumers use beg + cnt) fused with graph-boundary build.
// ---------------------------------------------------------------------------
__device__ __forceinline__ int batch_at(const void* b_raw, int i, int is32)
{
    int g = is32 ? ((const int*)b_raw)[i] : (int)((const long long*)b_raw)[i];
    g &= 0x7fffffff;
    return (g < NG) ? g : (NG - 1);
}

__global__ void k_scan_bounds(const void* __restrict__ b_raw)
{
    __shared__ int s[256];
    __shared__ int base_sh;
    const int tid = threadIdx.x;
    const int i = blockIdx.x * 256 + tid;
    const int v = (i < NN) ? g_cnt[i] : 0;
    s[tid] = v;
    __syncthreads();
#pragma unroll
    for (int d = 1; d < 256; d <<= 1) {
        const int t = (tid >= d) ? s[tid - d] : 0;
        __syncthreads();
        s[tid] += t;
        __syncthreads();
    }
    if (tid == 255) base_sh = atomicAdd(&g_total, s[255]);
    __syncthreads();
    if (i < NN) {
        const int o = base_sh + s[tid] - v;
        g_off[i] = o;
        g_cur[i] = o;
    }

    if (i < NN) {
        const int is32 = g_flag_b;
        const int g  = batch_at(b_raw, i, is32);
        const int gp = (i == 0) ? -1 : batch_at(b_raw, i - 1, is32);
        for (int q = gp + 1; q <= g; q++) g_gstart[q] = i;
        if (i == NN - 1)
            for (int q = g + 1; q <= NG; q++) g_gstart[q] = NN;
    }
}

// ---------------------------------------------------------------------------
// Kernel 4 (fused, block-partitioned): blocks [0,SCBLK) scatter edges into CSR;
// blocks [SCBLK, SCBLK+NBLK) run GEMM1.
// GEMM1: [50000,200] @ [W1r|W1l][200,64], packed f32x2.
//   cols 0..31 -> g_tr_a (messages) ; cols 32..63 -> g_root_a (+bias)
// ---------------------------------------------------------------------------
__global__ __launch_bounds__(256) void k_scatter_gemm1(const float* __restrict__ x,
                                                       const float* __restrict__ Wr,
                                                       const float* __restrict__ Wl,
                                                       const float* __restrict__ b)
{
    if (blockIdx.x < SCBLK) {
        const int e = blockIdx.x * 256 + threadIdx.x;
        if (e >= NE) return;
        const int pos = atomicAdd(&g_cur[g_dsti[e]], 1);
        g_esrc[pos] = g_srci[e];
        return;
    }

    __shared__ __align__(16) float Xs[8 * 256];   // [k][node]
    __shared__ __align__(16) float Wsc[8 * 64];   // [k][col]
    __shared__ float bs[32];

    const int tid = threadIdx.x;
    const int n0  = (blockIdx.x - SCBLK) * 256;
    if (tid < 32) bs[tid] = b[tid];

    const int cg = tid & 7;
    const int ng = tid >> 3;

    unsigned long long acc2[8][4];
#pragma unroll
    for (int i = 0; i < 8; i++)
#pragma unroll
        for (int j = 0; j < 4; j++) acc2[i][j] = 0ULL;

    const int  nld = n0 + tid;
    const bool vld = nld < NN;
    const float4* xrow = reinterpret_cast<const float4*>(x + (long)nld * DIN);
    const int kidx = tid >> 6, cidx = tid & 63;

    for (int k0 = 0; k0 < DIN; k0 += 8) {
        float4 xa = make_float4(0.f, 0.f, 0.f, 0.f), xb = xa;
        if (vld) { xa = xrow[k0 >> 2]; xb = xrow[(k0 >> 2) + 1]; }
        const int k1 = k0 + kidx, k2 = k1 + 4;
        const float w1 = (cidx < 32) ? Wr[k1 * 32 + cidx] : Wl[k1 * 32 + cidx - 32];
        const float w2 = (cidx < 32) ? Wr[k2 * 32 + cidx] : Wl[k2 * 32 + cidx - 32];

        __syncthreads();
        Xs[0 * 256 + tid] = xa.x; Xs[1 * 256 + tid] = xa.y;
        Xs[2 * 256 + tid] = xa.z; Xs[3 * 256 + tid] = xa.w;
        Xs[4 * 256 + tid] = xb.x; Xs[5 * 256 + tid] = xb.y;
        Xs[6 * 256 + tid] = xb.z; Xs[7 * 256 + tid] = xb.w;
        Wsc[kidx * 64 + cidx]       = w1;
        Wsc[(kidx + 4) * 64 + cidx] = w2;
        __syncthreads();

#pragma unroll
        for (int kk = 0; kk < 8; kk++) {
            const float4* xp = reinterpret_cast<const float4*>(Xs + kk * 256 + ng * 8);
            const float4 a0 = xp[0], a1 = xp[1];
            const unsigned long long* wp =
                reinterpret_cast<const unsigned long long*>(Wsc + kk * 64 + cg * 8);
            const unsigned long long w0 = wp[0], w1p = wp[1], w2p = wp[2], w3p = wp[3];
            const float xv[8] = {a0.x, a0.y, a0.z, a0.w, a1.x, a1.y, a1.z, a1.w};
#pragma unroll
            for (int i = 0; i < 8; i++) {
                unsigned long long xd;
                DUP_X2(xd, xv[i]);
                FMA_X2(acc2[i][0], xd, w0);
                FMA_X2(acc2[i][1], xd, w1p);
                FMA_X2(acc2[i][2], xd, w2p);
                FMA_X2(acc2[i][3], xd, w3p);
            }
        }
    }

    const int c0 = cg * 8;
#pragma unroll
    for (int i = 0; i < 8; i++) {
        const int node = n0 + ng * 8 + i;
        if (node >= NN) continue;
        float c[8];
#pragma unroll
        for (int j = 0; j < 4; j++) UNPK_X2(c[2 * j], c[2 * j + 1], acc2[i][j]);
        float4 lo = make_float4(c[0], c[1], c[2], c[3]);
        float4 hi = make_float4(c[4], c[5], c[6], c[7]);
        if (cg < 4) {
            *reinterpret_cast<float4*>(g_tr_a + node * DH + c0)     = lo;
            *reinterpret_cast<float4*>(g_tr_a + node * DH + c0 + 4) = hi;
        } else {
            const int cc = c0 - 32;
            lo.x += bs[cc + 0]; lo.y += bs[cc + 1]; lo.z += bs[cc + 2]; lo.w += bs[cc + 3];
            hi.x += bs[cc + 4]; hi.y += bs[cc + 5]; hi.z += bs[cc + 6]; hi.w += bs[cc + 7];
            *reinterpret_cast<float4*>(g_root_a + node * DH + cc)     = lo;
            *reinterpret_cast<float4*>(g_root_a + node * DH + cc + 4) = hi;
        }
    }
}

// ---------------------------------------------------------------------------
// Fused layer kernel (layers 1->2, 2->3): warp per node. Buffers selected by
// `sel` IN DEVICE CODE (sel=0: a->b, sel=1: b->a).
//   s = sum_{src->node} tr_in[src];  h = elu(s + root_in[node])
//   tr_out[node] = h @ Wr ; root_out[node] = h @ Wl + b
// ---------------------------------------------------------------------------
__global__ __launch_bounds__(256) void k_flayer(int sel,
                                                const float* __restrict__ Wr,
                                                const float* __restrict__ Wl,
                                                const float* __restrict__ b)
{
    __shared__ __align__(16) unsigned long long Wp[32 * 32];  // [k][lane]=(Wr,Wl)
    __shared__ float bs[32];
    __shared__ float hs[8][32];

    const int tid = threadIdx.x;
    for (int i = tid; i < 1024; i += 256) {
        const int k = i >> 5, c = i & 31;
        unsigned long long p;
        PACK_X2(p, Wr[k * 32 + c], Wl[k * 32 + c]);
        Wp[i] = p;
    }
    if (tid < 32) bs[tid] = b[tid];
    __syncthreads();

    const float* tr_in   = sel ? g_tr_b   : g_tr_a;
    const float* root_in = sel ? g_root_b : g_root_a;
    float* tr_out   = sel ? g_tr_a   : g_tr_b;
    float* root_out = sel ? g_root_a : g_root_b;

    const int w    = tid >> 5;
    const int lane = tid & 31;
    const int node = (blockIdx.x << 3) + w;
    if (node >= NN) return;

    const int beg = g_off[node];
    const int end = beg + g_cnt[node];
    float acc = 0.f;
    int k = beg;
    for (; k + 3 < end; k += 4) {
        const int s0 = g_esrc[k + 0], s1 = g_esrc[k + 1];
        const int s2 = g_esrc[k + 2], s3 = g_esrc[k + 3];
        acc += tr_in[s0 * DH + lane] + tr_in[s1 * DH + lane]
             + tr_in[s2 * DH + lane] + tr_in[s3 * DH + lane];
    }
    for (; k < end; k++) acc += tr_in[g_esrc[k] * DH + lane];

    const float h = elu1(acc + root_in[node * DH + lane]);
    hs[w][lane] = h;
    __syncwarp();

    unsigned long long a2 = 0ULL;
#pragma unroll
    for (int kk = 0; kk < 32; kk++) {
        unsigned long long hd;
        DUP_X2(hd, hs[w][kk]);                    // LDS broadcast
        FMA_X2(a2, hd, Wp[kk * 32 + lane]);
    }
    float m, r;
    UNPK_X2(m, r, a2);
    tr_out[node * DH + lane]   = m;
    root_out[node * DH + lane] = r + bs[lane];
}

// ---------------------------------------------------------------------------
// Fused layer 3 + pool: reads a-buffers (written by sel=1 flayer call).
// h = elu(aggr + root); atomicAdd into per-graph sums.
// ---------------------------------------------------------------------------
__global__ __launch_bounds__(256) void k_flayer3_pool(const void* __restrict__ b_raw)
{
    const int tid  = threadIdx.x;
    const int w    = tid >> 5;
    const int lane = tid & 31;
    const int node = (blockIdx.x << 3) + w;
    if (node >= NN) return;

    const int beg = g_off[node];
    const int end = beg + g_cnt[node];
    float acc = 0.f;
    int k = beg;
    for (; k + 3 < end; k += 4) {
        const int s0 = g_esrc[k + 0], s1 = g_esrc[k + 1];
        const int s2 = g_esrc[k + 2], s3 = g_esrc[k + 3];
        acc += g_tr_a[s0 * DH + lane] + g_tr_a[s1 * DH + lane]
             + g_tr_a[s2 * DH + lane] + g_tr_a[s3 * DH + lane];
    }
    for (; k < end; k++) acc += g_tr_a[g_esrc[k] * DH + lane];

    const float h = elu1(acc + g_root_a[node * DH + lane]);
    const int g = batch_at(b_raw, node, g_flag_b);
    atomicAdd(&g_sums[g * DH + lane], h);         // coalesced 128B atomic row
}

// ---------------------------------------------------------------------------
// Head: pooled mean -> linear[32,2] -> log_softmax
// ---------------------------------------------------------------------------
__global__ void k_head(const float* __restrict__ Wlin, const float* __restrict__ blin,
                       float* __restrict__ out)
{
    const int gph = threadIdx.x;
    if (gph >= NG) return;
    const int cnt = g_gstart[gph + 1] - g_gstart[gph];
    const float inv = 1.f / fmaxf((float)cnt, 1.f);
    float l0 = blin[0], l1 = blin[1];
#pragma unroll
    for (int c = 0; c < DH; c++) {
        const float p = g_sums[gph * DH + c] * inv;
        l0 += p * Wlin[c * 2 + 0];
        l1 += p * Wlin[c * 2 + 1];
    }
    const float m   = fmaxf(l0, l1);
    const float lse = m + logf(expf(l0 - m) + expf(l1 - m));
    out[gph * 2 + 0] = l0 - lse;
    out[gph * 2 + 1] = l1 - lse;
}

// ---------------------------------------------------------------------------
extern "C" void kernel_launch(void* const* d_in, const int* in_sizes, int n_in,
                              void* d_out, int out_size)
{
    const void *p_x = 0, *p_ei = 0, *p_batch = 0;
    const void *p_W1[2] = {0, 0};
    const void *p_W23[4] = {0, 0, 0, 0};
    const void *p_b[3] = {0, 0, 0};
    const void *p_Wlin = 0, *p_blin = 0;
    int n64 = 0, n1024 = 0, n32 = 0;
    for (int i = 0; i < n_in; i++) {
        const int s = in_sizes[i];
        if      (s == NN * DIN) p_x = d_in[i];
        else if (s == 2 * NE)   p_ei = d_in[i];
        else if (s == NN)       p_batch = d_in[i];
        else if (s == DIN * DH) { if (n64 < 2) p_W1[n64++] = d_in[i]; }
        else if (s == DH * DH)  { if (n1024 < 4) p_W23[n1024++] = d_in[i]; }
        else if (s == DH)       { if (n32 < 3) p_b[n32++] = d_in[i]; }
        else if (s == DH * 2)   p_Wlin = d_in[i];
        else if (s == 2)        p_blin = d_in[i];
    }
    const float* x    = (const float*)p_x;
    const float* W1r  = (const float*)p_W1[0];
    const float* W1l  = (const float*)p_W1[1];
    const float* b1   = (const float*)p_b[0];
    const float* W2r  = (const float*)p_W23[0];
    const float* W2l  = (const float*)p_W23[1];
    const float* b2   = (const float*)p_b[1];
    const float* W3r  = (const float*)p_W23[2];
    const float* W3l  = (const float*)p_W23[3];
    const float* b3   = (const float*)p_b[2];
    const float* Wlin = (const float*)p_Wlin;
    const float* blin = (const float*)p_blin;
    float* out = (float*)d_out;

    const int FBLKS = (NN + 7) / 8;               // 6250 (warp per node)

    k_detect_zero<<<NBLK, 256>>>((const unsigned*)p_ei, (const unsigned*)p_batch);
    k_conv_hist<<<SCBLK, 256>>>(p_ei);
    k_scan_bounds<<<NBLK, 256>>>(p_batch);
    k_scatter_gemm1<<<SCBLK + NBLK, 256>>>(x, W1r, W1l, b1);
    k_flayer<<<FBLKS, 256>>>(0, W2r, W2l, b2);    // a -> b (layer 1 act + layer 2 linear)
    k_flayer<<<FBLKS, 256>>>(1, W3r, W3l, b3);    // b -> a (layer 2 act + layer 3 linear)
    k_flayer3_pool<<<FBLKS, 256>>>(p_batch);      // layer 3 act + pool
    k_head<<<1, 64>>>(Wlin, blin, out);
}

// round 8
// speedup vs baseline: 1.2491x; 1.0685x over previous
#include <cuda_runtime.h>
#include <math.h>

#define NN 50000
#define NE 400000
#define NG 64
#define DIN 200
#define DH 32
#define NBLK 196    // ceil(NN/256)
#define EBLK 1563   // ceil(NE/256)
#define GBLK 391    // ceil(NN/128)   (GEMM blocks, 128 nodes each)
#define SCB2 3125   // ceil(NE/128)   (scatter blocks, 128 threads)

// ---------------- scratch (device globals — no allocation allowed) ----------
// NOTE: never pass these as kernel args from host code (host shadow symbol +
// ATS silently reads zeros). Select ping-pong buffers with an int in device code.
__device__ __align__(16) float g_tr_a[NN * DH];
__device__ __align__(16) float g_tr_b[NN * DH];
__device__ __align__(16) float g_root_a[NN * DH];
__device__ __align__(16) float g_root_b[NN * DH];
__device__ float g_sums[NG * DH];

__device__ int g_srci[NE];
__device__ int g_dsti[NE];
__device__ int g_flag_ei;    // nonzero -> edge_index is int32
__device__ int g_flag_b;     // nonzero -> batch is int32

__device__ int g_cnt[NN];
__device__ int g_off[NN];
__device__ int g_cur[NN];
__device__ int g_total;
__device__ int g_esrc[NE];
__device__ int g_gstart[NG + 1];

__device__ __forceinline__ float elu1(float v) { return v > 0.f ? v : expm1f(v); }

#define FMA_X2(acc, a, b) \
    asm("fma.rn.f32x2 %0, %1, %2, %0;" : "+l"(acc) : "l"(a), "l"(b))
#define DUP_X2(out, x) \
    asm("mov.b64 %0, {%1, %1};" : "=l"(out) : "r"(__float_as_uint(x)))
#define UNPK_X2(lo, hi, in) \
    asm("mov.b64 {%0, %1}, %2;" : "=f"(lo), "=f"(hi) : "l"(in))
#define PACK_X2(out, lo, hi) \
    asm("mov.b64 %0, {%1, %2};" : "=l"(out) : "f"(lo), "f"(hi))

// ---------------------------------------------------------------------------
// Kernel 1: zero scratch + dtype detection (sample odd 32-bit words: int64
// values < 2^31 have zero high words; int32 payloads essentially never do)
// ---------------------------------------------------------------------------
__global__ void k_detect_zero(const unsigned* __restrict__ ei_w,
                              const unsigned* __restrict__ b_w)
{
    const int i = blockIdx.x * blockDim.x + threadIdx.x;
    if (i < NN) g_cnt[i] = 0;
    if (i < NG * DH) g_sums[i] = 0.f;
    if (i == 0) g_total = 0;

    if (blockIdx.x == 0) {
        __shared__ int s_ei, s_b;
        const int tid = threadIdx.x;
        if (tid == 0) { s_ei = 0; s_b = 0; }
        __syncthreads();
        { const int k = tid * 1562;  if (ei_w[2 * k + 1] != 0) atomicOr(&s_ei, 1); }
        { const int k = 24744 + tid; if (b_w[2 * k + 1] != 0)  atomicOr(&s_b, 1); }
        __syncthreads();
        if (tid == 0) { g_flag_ei = s_ei; g_flag_b = s_b; }
    }
}

// ---------------------------------------------------------------------------
// Kernel 2: decode edges (either dtype) + clamp + dst histogram
// ---------------------------------------------------------------------------
__global__ void k_conv_hist(const void* __restrict__ ei_raw)
{
    const int e = blockIdx.x * blockDim.x + threadIdx.x;
    if (e >= NE) return;
    int s, d;
    if (g_flag_ei) {
        const int* p = (const int*)ei_raw;
        s = p[e]; d = p[NE + e];
    } else {
        const long long* p = (const long long*)ei_raw;
        s = (int)p[e]; d = (int)p[NE + e];
    }
    s &= 0x7fffffff; d &= 0x7fffffff;
    s = (s < NN) ? s : 0;
    d = (d < NN) ? d : 0;
    g_srci[e] = s;
    g_dsti[e] = d;
    atomicAdd(&g_cnt[d], 1);
}

// ---------------------------------------------------------------------------
// Kernel 3: single-pass scan (block scan + atomic base; bases need not be
// monotone since consumers use beg + cnt) fused with graph-boundary build.
// ---------------------------------------------------------------------------
__device__ __forceinline__ int batch_at(const void* b_raw, int i, int is32)
{
    int g = is32 ? ((const int*)b_raw)[i] : (int)((const long long*)b_raw)[i];
    g &= 0x7fffffff;
    return (g < NG) ? g : (NG - 1);
}

__global__ void k_scan_bounds(const void* __restrict__ b_raw)
{
    __shared__ int s[256];
    __shared__ int base_sh;
    const int tid = threadIdx.x;
    const int i = blockIdx.x * 256 + tid;
    const int v = (i < NN) ? g_cnt[i] : 0;
    s[tid] = v;
    __syncthreads();
#pragma unroll
    for (int d = 1; d < 256; d <<= 1) {
        const int t = (tid >= d) ? s[tid - d] : 0;
        __syncthreads();
        s[tid] += t;
        __syncthreads();
    }
    if (tid == 255) base_sh = atomicAdd(&g_total, s[255]);
    __syncthreads();
    if (i < NN) {
        const int o = base_sh + s[tid] - v;
        g_off[i] = o;
        g_cur[i] = o;
    }

    if (i < NN) {
        const int is32 = g_flag_b;
        const int g  = batch_at(b_raw, i, is32);
        const int gp = (i == 0) ? -1 : batch_at(b_raw, i - 1, is32);
        for (int q = gp + 1; q <= g; q++) g_gstart[q] = i;
        if (i == NN - 1)
            for (int q = g + 1; q <= NG; q++) g_gstart[q] = NN;
    }
}

// ---------------------------------------------------------------------------
// Kernel 4 (fused): blocks [0,GBLK) = GEMM1 (first, start in wave 1);
// blocks [GBLK, GBLK+SCB2) = CSR scatter streaming through leftover slots.
// GEMM1: [50000,200] @ [W1r|W1l][200,64], packed f32x2, double-buffered smem,
// 128 threads / 128 nodes / 64 cols, one __syncthreads per K-tile.
// ---------------------------------------------------------------------------
__global__ __launch_bounds__(128) void k_gemm1_scatter(const float* __restrict__ x,
                                                       const float* __restrict__ Wr,
                                                       const float* __restrict__ Wl,
                                                       const float* __restrict__ b)
{
    if (blockIdx.x >= GBLK) {
        const int e = (blockIdx.x - GBLK) * 128 + threadIdx.x;
        if (e >= NE) return;
        const int pos = atomicAdd(&g_cur[g_dsti[e]], 1);
        g_esrc[pos] = g_srci[e];
        return;
    }

    __shared__ __align__(16) float Xs[2][8 * 128];   // [buf][k][node]
    __shared__ __align__(16) float Wsc[2][8 * 64];   // [buf][k*64+c]
    __shared__ float bs[32];

    const int tid = threadIdx.x;
    const int n0  = blockIdx.x * 128;
    if (tid < 32) bs[tid] = b[tid];

    const int cg = tid & 7;        // col group (8 cols = 4 packed pairs)
    const int ng = tid >> 3;       // node group (8 nodes), 0..15

    unsigned long long acc2[8][4];
#pragma unroll
    for (int i = 0; i < 8; i++)
#pragma unroll
        for (int j = 0; j < 4; j++) acc2[i][j] = 0ULL;

    const int  nld = n0 + tid;
    const bool vld = nld < NN;
    const float4* xrow = reinterpret_cast<const float4*>(x + (long)nld * DIN);

    float4 xa, xb;
    float  wv[4];

#define LOAD_TILE(t)                                                          \
    do {                                                                      \
        xa = make_float4(0.f, 0.f, 0.f, 0.f); xb = xa;                        \
        if (vld) { xa = xrow[(t) * 2]; xb = xrow[(t) * 2 + 1]; }              \
        _Pragma("unroll")                                                     \
        for (int j = 0; j < 4; j++) {                                         \
            const int idx = j * 128 + tid;       /* 0..511 = k*64+c */        \
            const int kk = idx >> 6, c = idx & 63;                            \
            wv[j] = (c < 32) ? Wr[((t) * 8 + kk) * 32 + c]                    \
                             : Wl[((t) * 8 + kk) * 32 + c - 32];              \
        }                                                                     \
    } while (0)

#define STORE_TILE(bf)                                                        \
    do {                                                                      \
        Xs[bf][0 * 128 + tid] = xa.x; Xs[bf][1 * 128 + tid] = xa.y;           \
        Xs[bf][2 * 128 + tid] = xa.z; Xs[bf][3 * 128 + tid] = xa.w;           \
        Xs[bf][4 * 128 + tid] = xb.x; Xs[bf][5 * 128 + tid] = xb.y;           \
        Xs[bf][6 * 128 + tid] = xb.z; Xs[bf][7 * 128 + tid] = xb.w;           \
        _Pragma("unroll")                                                     \
        for (int j = 0; j < 4; j++) Wsc[bf][j * 128 + tid] = wv[j];           \
    } while (0)

    LOAD_TILE(0);
    STORE_TILE(0);
    __syncthreads();

    int buf = 0;
    for (int t = 0; t < 25; t++) {
        if (t < 24) LOAD_TILE(t + 1);            // LDG in flight during compute

#pragma unroll
        for (int kk = 0; kk < 8; kk++) {
            const float4* xp = reinterpret_cast<const float4*>(Xs[buf] + kk * 128 + ng * 8);
            const float4 a0 = xp[0], a1 = xp[1];
            const unsigned long long* wp =
                reinterpret_cast<const unsigned long long*>(Wsc[buf] + kk * 64 + cg * 8);
            const unsigned long long w0 = wp[0], w1p = wp[1], w2p = wp[2], w3p = wp[3];
            const float xv[8] = {a0.x, a0.y, a0.z, a0.w, a1.x, a1.y, a1.z, a1.w};
#pragma unroll
            for (int i = 0; i < 8; i++) {
                unsigned long long xd;
                DUP_X2(xd, xv[i]);
                FMA_X2(acc2[i][0], xd, w0);
                FMA_X2(acc2[i][1], xd, w1p);
                FMA_X2(acc2[i][2], xd, w2p);
                FMA_X2(acc2[i][3], xd, w3p);
            }
        }

        if (t < 24) STORE_TILE(buf ^ 1);         // other buffer: race-free
        __syncthreads();
        buf ^= 1;
    }
#undef LOAD_TILE
#undef STORE_TILE

    const int c0 = cg * 8;
#pragma unroll
    for (int i = 0; i < 8; i++) {
        const int node = n0 + ng * 8 + i;
        if (node >= NN) continue;
        float c[8];
#pragma unroll
        for (int j = 0; j < 4; j++) UNPK_X2(c[2 * j], c[2 * j + 1], acc2[i][j]);
        float4 lo = make_float4(c[0], c[1], c[2], c[3]);
        float4 hi = make_float4(c[4], c[5], c[6], c[7]);
        if (cg < 4) {
            *reinterpret_cast<float4*>(g_tr_a + node * DH + c0)     = lo;
            *reinterpret_cast<float4*>(g_tr_a + node * DH + c0 + 4) = hi;
        } else {
            const int cc = c0 - 32;
            lo.x += bs[cc + 0]; lo.y += bs[cc + 1]; lo.z += bs[cc + 2]; lo.w += bs[cc + 3];
            hi.x += bs[cc + 4]; hi.y += bs[cc + 5]; hi.z += bs[cc + 6]; hi.w += bs[cc + 7];
            *reinterpret_cast<float4*>(g_root_a + node * DH + cc)     = lo;
            *reinterpret_cast<float4*>(g_root_a + node * DH + cc + 4) = hi;
        }
    }
}

// ---------------------------------------------------------------------------
// Fused layer kernel (layers 1->2, 2->3): warp per node; buffers picked by sel
// in device code (sel=0: a->b, sel=1: b->a).
// ---------------------------------------------------------------------------
__global__ __launch_bounds__(256) void k_flayer(int sel,
                                                const float* __restrict__ Wr,
                                                const float* __restrict__ Wl,
                                                const float* __restrict__ b)
{
    __shared__ __align__(16) unsigned long long Wp[32 * 32];  // [k][lane]=(Wr,Wl)
    __shared__ float bs[32];
    __shared__ float hs[8][32];

    const int tid = threadIdx.x;
    for (int i = tid; i < 1024; i += 256) {
        const int k = i >> 5, c = i & 31;
        unsigned long long p;
        PACK_X2(p, Wr[k * 32 + c], Wl[k * 32 + c]);
        Wp[i] = p;
    }
    if (tid < 32) bs[tid] = b[tid];
    __syncthreads();

    const float* tr_in   = sel ? g_tr_b   : g_tr_a;
    const float* root_in = sel ? g_root_b : g_root_a;
    float* tr_out   = sel ? g_tr_a   : g_tr_b;
    float* root_out = sel ? g_root_a : g_root_b;

    const int w    = tid >> 5;
    const int lane = tid & 31;
    const int node = (blockIdx.x << 3) + w;
    if (node >= NN) return;

    const int beg = g_off[node];
    const int end = beg + g_cnt[node];
    float acc = 0.f;
    int k = beg;
    for (; k + 3 < end; k += 4) {
        const int s0 = g_esrc[k + 0], s1 = g_esrc[k + 1];
        const int s2 = g_esrc[k + 2], s3 = g_esrc[k + 3];
        acc += tr_in[s0 * DH + lane] + tr_in[s1 * DH + lane]
             + tr_in[s2 * DH + lane] + tr_in[s3 * DH + lane];
    }
    for (; k < end; k++) acc += tr_in[g_esrc[k] * DH + lane];

    const float h = elu1(acc + root_in[node * DH + lane]);
    hs[w][lane] = h;
    __syncwarp();

    unsigned long long a2 = 0ULL;
#pragma unroll
    for (int kk = 0; kk < 32; kk++) {
        unsigned long long hd;
        DUP_X2(hd, hs[w][kk]);                    // LDS broadcast
        FMA_X2(a2, hd, Wp[kk * 32 + lane]);
    }
    float m, r;
    UNPK_X2(m, r, a2);
    tr_out[node * DH + lane]   = m;
    root_out[node * DH + lane] = r + bs[lane];
}

// ---------------------------------------------------------------------------
// Fused layer 3 + pool: reads a-buffers; h = elu(aggr + root); atomic pool.
// ---------------------------------------------------------------------------
__global__ __launch_bounds__(256) void k_flayer3_pool(const void* __restrict__ b_raw)
{
    const int tid  = threadIdx.x;
    const int w    = tid >> 5;
    const int lane = tid & 31;
    const int node = (blockIdx.x << 3) + w;
    if (node >= NN) return;

    const int beg = g_off[node];
    const int end = beg + g_cnt[node];
    float acc = 0.f;
    int k = beg;
    for (; k + 3 < end; k += 4) {
        const int s0 = g_esrc[k + 0], s1 = g_esrc[k + 1];
        const int s2 = g_esrc[k + 2], s3 = g_esrc[k + 3];
        acc += g_tr_a[s0 * DH + lane] + g_tr_a[s1 * DH + lane]
             + g_tr_a[s2 * DH + lane] + g_tr_a[s3 * DH + lane];
    }
    for (; k < end; k++) acc += g_tr_a[g_esrc[k] * DH + lane];

    const float h = elu1(acc + g_root_a[node * DH + lane]);
    const int g = batch_at(b_raw, node, g_flag_b);
    atomicAdd(&g_sums[g * DH + lane], h);
}

// ---------------------------------------------------------------------------
// Head: pooled mean -> linear[32,2] -> log_softmax
// ---------------------------------------------------------------------------
__global__ void k_head(const float* __restrict__ Wlin, const float* __restrict__ blin,
                       float* __restrict__ out)
{
    const int gph = threadIdx.x;
    if (gph >= NG) return;
    const int cnt = g_gstart[gph + 1] - g_gstart[gph];
    const float inv = 1.f / fmaxf((float)cnt, 1.f);
    float l0 = blin[0], l1 = blin[1];
#pragma unroll
    for (int c = 0; c < DH; c++) {
        const float p = g_sums[gph * DH + c] * inv;
        l0 += p * Wlin[c * 2 + 0];
        l1 += p * Wlin[c * 2 + 1];
    }
    const float m   = fmaxf(l0, l1);
    const float lse = m + logf(expf(l0 - m) + expf(l1 - m));
    out[gph * 2 + 0] = l0 - lse;
    out[gph * 2 + 1] = l1 - lse;
}

// ---------------------------------------------------------------------------
extern "C" void kernel_launch(void* const* d_in, const int* in_sizes, int n_in,
                              void* d_out, int out_size)
{
    const void *p_x = 0, *p_ei = 0, *p_batch = 0;
    const void *p_W1[2] = {0, 0};
    const void *p_W23[4] = {0, 0, 0, 0};
    const void *p_b[3] = {0, 0, 0};
    const void *p_Wlin = 0, *p_blin = 0;
    int n64 = 0, n1024 = 0, n32 = 0;
    for (int i = 0; i < n_in; i++) {
        const int s = in_sizes[i];
        if      (s == NN * DIN) p_x = d_in[i];
        else if (s == 2 * NE)   p_ei = d_in[i];
        else if (s == NN)       p_batch = d_in[i];
        else if (s == DIN * DH) { if (n64 < 2) p_W1[n64++] = d_in[i]; }
        else if (s == DH * DH)  { if (n1024 < 4) p_W23[n1024++] = d_in[i]; }
        else if (s == DH)       { if (n32 < 3) p_b[n32++] = d_in[i]; }
        else if (s == DH * 2)   p_Wlin = d_in[i];
        else if (s == 2)        p_blin = d_in[i];
    }
    const float* x    = (const float*)p_x;
    const float* W1r  = (const float*)p_W1[0];
    const float* W1l  = (const float*)p_W1[1];
    const float* b1   = (const float*)p_b[0];
    const float* W2r  = (const float*)p_W23[0];
    const float* W2l  = (const float*)p_W23[1];
    const float* b2   = (const float*)p_b[1];
    const float* W3r  = (const float*)p_W23[2];
    const float* W3l  = (const float*)p_W23[3];
    const float* b3   = (const float*)p_b[2];
    const float* Wlin = (const float*)p_Wlin;
    const float* blin = (const float*)p_blin;
    float* out = (float*)d_out;

    const int FBLKS = (NN + 7) / 8;               // 6250 (warp per node)

    k_detect_zero<<<NBLK, 256>>>((const unsigned*)p_ei, (const unsigned*)p_batch);
    k_conv_hist<<<EBLK, 256>>>(p_ei);
    k_scan_bounds<<<NBLK, 256>>>(p_batch);
    k_gemm1_scatter<<<GBLK + SCB2, 128>>>(x, W1r, W1l, b1);
    k_flayer<<<FBLKS, 256>>>(0, W2r, W2l, b2);    // a -> b (layer 1 act + layer 2 linear)
    k_flayer<<<FBLKS, 256>>>(1, W3r, W3l, b3);    // b -> a (layer 2 act + layer 3 linear)
    k_flayer3_pool<<<FBLKS, 256>>>(p_batch);      // layer 3 act + pool
    k_head<<<1, 64>>>(Wlin, blin, out);
}